// round 10
// baseline (speedup 1.0000x reference)
#include <cuda_runtime.h>
#include <cuda_bf16.h>
#include <math.h>
#include <stdint.h>

#define Bq 16
#define Tt 1024
#define Dd 512
#define CO 7
#define PRED 96
#define KK 8
#define LATENT 2048
#define NFREQ 511
#define TP (Tt + PRED)

#define RES3_OFF 0
#define LVL_OFF  (Bq*Tt*Dd)
#define GROW_OFF (LVL_OFF + Bq*Tt*CO)
#define SEAS_OFF (GROW_OFF + Bq*(Tt+1)*Dd)

#define PI2 6.283185307179586476925286766559f

// ---------------- scratch ----------------
__device__ float g_Xre[(size_t)Bq*NFREQ*Dd];
__device__ float g_Xim[(size_t)Bq*NFREQ*Dd];
__device__ int   g_fr[Bq*Dd*KK];
__device__ float g_amp[Bq*Dd*KK];
__device__ float g_ph[Bq*Dd*KK];
__device__ float g_tkv[(size_t)Bq*8*Dd*KK];
__device__ int   g_tki[(size_t)Bq*8*Dd*KK];
__device__ float g_res1[(size_t)Bq*Tt*Dd];
__device__ float g_v[(size_t)Bq*Tt*Dd];
__device__ float g_smcat[(size_t)Bq*(Tt+1)*Dd];
__device__ float g_res2[(size_t)Bq*Tt*Dd];
__device__ float g_ffh[(size_t)Bq*Tt*LATENT];
__device__ float g_ffy[(size_t)Bq*Tt*Dd];
__device__ float g_gp[Bq*Tt*CO];
__device__ float g_sp[Bq*Tt*CO];
// DFT twiddle matrix, hi/lo bf16 split: rows 0..511 cos(f=r+1), 512..1023 -sin
__device__ __nv_bfloat16 g_dwh[(size_t)1024*1024];
__device__ __nv_bfloat16 g_dwl[(size_t)1024*1024];
// x transposed + split: [b][d][t] bf16 hi/lo
__device__ __nv_bfloat16 g_xth[(size_t)Bq*Dd*Tt];
__device__ __nv_bfloat16 g_xtl[(size_t)Bq*Dd*Tt];
// tf32-prerounded weight buffer (max 2048*512)
__device__ float g_wtf[(size_t)2048*512];

// ---------------- helpers ----------------
__device__ __forceinline__ uint32_t f2tf(float x) {
    uint32_t u;
    asm("cvt.rna.tf32.f32 %0, %1;" : "=r"(u) : "f"(x));
    return u;
}
__device__ __forceinline__ float bf_round(float x) {
    return __bfloat162float(__float2bfloat16(x));
}
__device__ __forceinline__ void mma_bf16(float* c, const uint32_t* a, const uint32_t* b) {
    asm volatile(
        "mma.sync.aligned.m16n8k16.row.col.f32.bf16.bf16.f32 "
        "{%0,%1,%2,%3}, {%4,%5,%6,%7}, {%8,%9}, {%0,%1,%2,%3};"
        : "+f"(c[0]), "+f"(c[1]), "+f"(c[2]), "+f"(c[3])
        : "r"(a[0]), "r"(a[1]), "r"(a[2]), "r"(a[3]), "r"(b[0]), "r"(b[1]));
}
__device__ __forceinline__ uint32_t smem_u32(const void* p) {
    uint32_t a;
    asm("{ .reg .u64 t; cvta.to.shared.u64 t, %1; cvt.u32.u64 %0, t; }" : "=r"(a) : "l"(p));
    return a;
}
__device__ __forceinline__ void cp16(uint32_t dst, const void* src, int sz) {
    asm volatile("cp.async.cg.shared.global [%0], [%1], 16, %2;"
                 :: "r"(dst), "l"(src), "r"(sz));
}
#define CP_COMMIT() asm volatile("cp.async.commit_group;")
#define CP_WAIT2()  asm volatile("cp.async.wait_group 2;")

// ---------------- DFT twiddle precompute ----------------
__global__ void k_dftw() {
    for (int e = blockIdx.x * 256 + threadIdx.x; e < 1024 * 1024; e += 262144) {
        int row = e >> 10, t = e & 1023;
        int f = (row < 512) ? row + 1 : row - 511;
        int ph = (f * t) & 1023;
        float ang = (float)ph * (1.0f / 512.0f);
        float v = (row < 512) ? cospif(ang) : -sinpif(ang);
        float h = bf_round(v);
        g_dwh[e] = __float2bfloat16(h);
        g_dwl[e] = __float2bfloat16(v - h);
    }
}

// ---------------- x transpose + hi/lo bf16 split ----------------
__global__ void k_xt(const float* __restrict__ x) {
    __shared__ float t[32][33];
    int b = blockIdx.z;
    int t0 = blockIdx.x * 32, d0 = blockIdx.y * 32;
    int tx = threadIdx.x, ty = threadIdx.y;
    const float* xp = x + (size_t)b * Tt * Dd;
#pragma unroll
    for (int i = 0; i < 32; i += 8)
        t[ty + i][tx] = xp[(size_t)(t0 + ty + i) * Dd + d0 + tx];
    __syncthreads();
#pragma unroll
    for (int i = 0; i < 32; i += 8) {
        float v = t[tx][ty + i];
        float h = bf_round(v);
        size_t o = ((size_t)b * Dd + d0 + ty + i) * Tt + t0 + tx;
        g_xth[o] = __float2bfloat16(h);
        g_xtl[o] = __float2bfloat16(v - h);
    }
}

// ---------------- cp.async tensor-core DFT ----------------
__device__ __forceinline__ void dft_store(int row, int col, float v0, float v1, int b) {
    if (row < 512) {
        if (row < 511)
            *(float2*)&g_Xre[((size_t)b * NFREQ + row) * Dd + col] = make_float2(v0, v1);
    } else {
        int rr = row - 512;
        if (rr < 511)
            *(float2*)&g_Xim[((size_t)b * NFREQ + rr) * Dd + col] = make_float2(v0, v1);
    }
}
__device__ __forceinline__ int dswz(int r, int c) {
    return r * 16 + ((c ^ ((r >> 1) & 3)) << 2);
}

#define DFT_SMEM (3 * 32768)

__global__ __launch_bounds__(256, 2)
void k_dftmm() {
    extern __shared__ uint32_t ds[];
    uint32_t sb = smem_u32(ds);
    int tid = threadIdx.x, lane = tid & 31, warp = tid >> 5;
    int warpM = warp >> 2, warpN = warp & 3;
    int bn = blockIdx.x * 128, bm = blockIdx.y * 128;
    int b = blockIdx.z;

    float acc[4][4][4];
#pragma unroll
    for (int i = 0; i < 4; i++)
#pragma unroll
        for (int j = 0; j < 4; j++)
#pragma unroll
            for (int q = 0; q < 4; q++) acc[i][j][q] = 0.f;

    int crow = tid >> 1;
    int cc0  = (tid & 1) * 2;
    const __nv_bfloat16* ga_h = g_dwh + (size_t)(bm + crow) * 1024;
    const __nv_bfloat16* ga_l = g_dwl + (size_t)(bm + crow) * 1024;
    const __nv_bfloat16* gb_h = g_xth + ((size_t)b * Dd + bn + crow) * Tt;
    const __nv_bfloat16* gb_l = g_xtl + ((size_t)b * Dd + bn + crow) * Tt;
    uint32_t so0 = (uint32_t)dswz(crow, cc0) * 4;
    uint32_t so1 = (uint32_t)dswz(crow, cc0 + 1) * 4;

    auto issue = [&](int c) {
        uint32_t base = sb + (uint32_t)(c % 3) * 32768;
        int k0 = c * 32;
        cp16(base + so0,         ga_h + k0 + cc0 * 8, 16);
        cp16(base + so1,         ga_h + k0 + cc0 * 8 + 8, 16);
        cp16(base + 8192 + so0,  ga_l + k0 + cc0 * 8, 16);
        cp16(base + 8192 + so1,  ga_l + k0 + cc0 * 8 + 8, 16);
        cp16(base + 16384 + so0, gb_h + k0 + cc0 * 8, 16);
        cp16(base + 16384 + so1, gb_h + k0 + cc0 * 8 + 8, 16);
        cp16(base + 24576 + so0, gb_l + k0 + cc0 * 8, 16);
        cp16(base + 24576 + so1, gb_l + k0 + cc0 * 8 + 8, 16);
    };

    issue(0); CP_COMMIT();
    issue(1); CP_COMMIT();
    issue(2); CP_COMMIT();

    int g = lane >> 2, cq = lane & 3;
    for (int c = 0; c < 32; c++) {
        CP_WAIT2();
        __syncthreads();

        const uint32_t* Ah = ds + (size_t)(c % 3) * 8192;
        const uint32_t* Al = Ah + 2048;
        const uint32_t* Bh = Ah + 4096;
        const uint32_t* Bl = Ah + 6144;
#pragma unroll
        for (int ks = 0; ks < 2; ks++) {
            int c0 = ks * 2, c1 = ks * 2 + 1;
            uint32_t af[4][4], bh[4][2], bx[4][2];
#pragma unroll
            for (int mt = 0; mt < 4; mt++) {
                int r = warpM * 64 + mt * 16 + g;
                af[mt][0] = Ah[dswz(r, c0) + cq];
                af[mt][1] = Ah[dswz(r + 8, c0) + cq];
                af[mt][2] = Ah[dswz(r, c1) + cq];
                af[mt][3] = Ah[dswz(r + 8, c1) + cq];
            }
#pragma unroll
            for (int nt = 0; nt < 4; nt++) {
                int n = warpN * 32 + nt * 8 + g;
                bh[nt][0] = Bh[dswz(n, c0) + cq];
                bh[nt][1] = Bh[dswz(n, c1) + cq];
            }
#pragma unroll
            for (int mt = 0; mt < 4; mt++)
#pragma unroll
                for (int nt = 0; nt < 4; nt++) mma_bf16(acc[mt][nt], af[mt], bh[nt]);
#pragma unroll
            for (int nt = 0; nt < 4; nt++) {
                int n = warpN * 32 + nt * 8 + g;
                bx[nt][0] = Bl[dswz(n, c0) + cq];
                bx[nt][1] = Bl[dswz(n, c1) + cq];
            }
#pragma unroll
            for (int mt = 0; mt < 4; mt++)
#pragma unroll
                for (int nt = 0; nt < 4; nt++) mma_bf16(acc[mt][nt], af[mt], bx[nt]);
#pragma unroll
            for (int mt = 0; mt < 4; mt++) {
                int r = warpM * 64 + mt * 16 + g;
                af[mt][0] = Al[dswz(r, c0) + cq];
                af[mt][1] = Al[dswz(r + 8, c0) + cq];
                af[mt][2] = Al[dswz(r, c1) + cq];
                af[mt][3] = Al[dswz(r + 8, c1) + cq];
            }
#pragma unroll
            for (int mt = 0; mt < 4; mt++)
#pragma unroll
                for (int nt = 0; nt < 4; nt++) mma_bf16(acc[mt][nt], af[mt], bh[nt]);
        }
        __syncthreads();
        if (c + 3 < 32) issue(c + 3);
        CP_COMMIT();
    }

#pragma unroll
    for (int mt = 0; mt < 4; mt++) {
        int r0 = bm + warpM * 64 + mt * 16 + g;
#pragma unroll
        for (int nt = 0; nt < 4; nt++) {
            int n0 = bn + warpN * 32 + nt * 8 + 2 * cq;
            dft_store(r0,     n0, acc[mt][nt][0], acc[mt][nt][1], b);
            dft_store(r0 + 8, n0, acc[mt][nt][2], acc[mt][nt][3], b);
        }
    }
}

// ---------------- top-K phase 1: per-chunk top-8 ----------------
// grid (8 chunks, Bq), 512 threads (d). Chunk c covers f in [c*64, min(c*64+64, 511)).
__global__ void k_topk1() {
    int d = threadIdx.x;
    int ch = blockIdx.x;
    int b = blockIdx.y;
    int f0 = ch * 64;
    int f1 = f0 + 64 < NFREQ ? f0 + 64 : NFREQ;

    float val[KK];
    int   idx[KK];
#pragma unroll
    for (int k = 0; k < KK; k++) { val[k] = -1.f; idx[k] = 0; }

    for (int f = f0; f < f1; f++) {
        size_t o = ((size_t)b * NFREQ + f) * Dd + d;
        float re = g_Xre[o], im = g_Xim[o];
        float m = re * re + im * im;
        if (m > val[KK - 1]) {
            int p = KK - 1;
            while (p > 0 && m > val[p - 1]) {
                val[p] = val[p - 1]; idx[p] = idx[p - 1]; p--;
            }
            val[p] = m; idx[p] = f;
        }
    }
    size_t base = (((size_t)b * 8 + ch) * Dd + d) * KK;
#pragma unroll
    for (int k = 0; k < KK; k++) {
        g_tkv[base + k] = val[k];
        g_tki[base + k] = idx[k];
    }
}

// ---------------- top-K phase 2: merge 8 sorted chunk lists ----------------
__global__ void k_topk2() {
    int d = threadIdx.x;
    int b = blockIdx.x;
    float val[KK];
    int   idx[KK];
#pragma unroll
    for (int k = 0; k < KK; k++) { val[k] = -1.f; idx[k] = 0; }

    for (int ch = 0; ch < 8; ch++) {
        size_t base = (((size_t)b * 8 + ch) * Dd + d) * KK;
#pragma unroll
        for (int k = 0; k < KK; k++) {
            float m = g_tkv[base + k];
            if (m > val[KK - 1]) {
                int fi = g_tki[base + k];
                int p = KK - 1;
                while (p > 0 && m > val[p - 1]) {
                    val[p] = val[p - 1]; idx[p] = idx[p - 1]; p--;
                }
                val[p] = m; idx[p] = fi;
            } else {
                break;   // chunk list is sorted descending
            }
        }
    }

    int obase = (b * Dd + d) * KK;
#pragma unroll
    for (int k = 0; k < KK; k++) {
        int f = idx[k];
        size_t o = ((size_t)b * NFREQ + f) * Dd + d;
        float re = g_Xre[o], im = g_Xim[o];
        float mag = sqrtf(re * re + im * im);
        g_fr[obase + k]  = f + 1;
        g_amp[obase + k] = 2.0f * mag * (1.0f / 1024.0f);
        g_ph[obase + k]  = atan2f(im, re);
    }
}

// ---------------- season synthesis + res1 ----------------
__global__ void k_season(const float* __restrict__ res,
                         float* __restrict__ season,
                         float* __restrict__ res1) {
    int d = threadIdx.x;
    int b = blockIdx.y;
    int t0 = blockIdx.x * 16;
    int base = (b * Dd + d) * KK;
    int fr[KK]; float am[KK], ph[KK];
#pragma unroll
    for (int k = 0; k < KK; k++) {
        fr[k] = g_fr[base + k]; am[k] = g_amp[base + k]; ph[k] = g_ph[base + k];
    }
    for (int tt = 0; tt < 16; tt++) {
        int t = t0 + tt;
        float sum = 0.f;
#pragma unroll
        for (int k = 0; k < KK; k++) {
            int id = (fr[k] * t) & 1023;
            sum += am[k] * __cosf((float)id * (PI2 / 1024.0f) + ph[k]);
        }
        season[((size_t)b * TP + t) * Dd + d] = sum;
        if (t < Tt) {
            size_t o = ((size_t)b * Tt + t) * Dd + d;
            res1[o] = res[o] - sum;
        }
    }
}

// ---------------- weight pre-round to tf32 ----------------
__global__ void k_wtf(const float* __restrict__ W, float* __restrict__ O, int n) {
    int i = blockIdx.x * 256 + threadIdx.x;
    if (i < n) O[i] = __uint_as_float(f2tf(W[i]));
}

// ================= tf32 cp.async multistage GEMM =================
#define GM_SMEM (4 * 16384)

template <int EPI>
__global__ __launch_bounds__(256, 2)
void k_mma(const float* __restrict__ A, const float* __restrict__ W,
           float* __restrict__ C, int M, int N, int K) {
    extern __shared__ uint32_t sm[];
    uint32_t sb = smem_u32(sm);

    int tid  = threadIdx.x;
    int lane = tid & 31;
    int warp = tid >> 5;
    int warpM = warp >> 2;
    int warpN = warp & 3;
    int brow = blockIdx.y * 128;
    int bcol = blockIdx.x * 128;
    int lr = lane >> 2;
    int lc = lane & 3;

    float acc[4][4][4];
#pragma unroll
    for (int i = 0; i < 4; i++)
#pragma unroll
        for (int j = 0; j < 4; j++)
#pragma unroll
            for (int q = 0; q < 4; q++) acc[i][j][q] = 0.f;

    int am  = tid >> 1;
    int akg = (tid & 1) * 2;
    int asz = (brow + am < M) ? 16 : 0;
    const float* a_base = A + (size_t)(brow + am) * K;
    uint32_t a_off0 = (uint32_t)(am * 16 + (((akg + 0) * 4) ^ (((am >> 1) & 3) << 2))) * 4;
    uint32_t a_off1 = (uint32_t)(am * 16 + (((akg + 1) * 4) ^ (((am >> 1) & 3) << 2))) * 4;

    int bkr = tid >> 4;
    int bn4 = (tid & 15) * 2;
    const float* b_base = W + (size_t)bkr * N + bcol;
    uint32_t b_off0 = (uint32_t)(8192 + (bkr * 128 + (((bn4 + 0) * 4) ^ ((bkr & 3) << 3))) * 4);
    uint32_t b_off1 = (uint32_t)(8192 + (bkr * 128 + (((bn4 + 1) * 4) ^ ((bkr & 3) << 3))) * 4);

    const int NC = K >> 4;

    auto issue = [&](int c) {
        uint32_t base = sb + (uint32_t)(c & 3) * 16384;
        int k0 = c * 16;
        cp16(base + a_off0, a_base + k0 + (akg + 0) * 4, asz);
        cp16(base + a_off1, a_base + k0 + (akg + 1) * 4, asz);
        cp16(base + b_off0, b_base + (size_t)k0 * N + (bn4 + 0) * 4, 16);
        cp16(base + b_off1, b_base + (size_t)k0 * N + (bn4 + 1) * 4, 16);
    };

    issue(0); CP_COMMIT();
    issue(1); CP_COMMIT();
    issue(2); CP_COMMIT();

    for (int c = 0; c < NC; c++) {
        CP_WAIT2();
        __syncthreads();
        if (c + 3 < NC) issue(c + 3);
        CP_COMMIT();

        const float*    asf = (const float*)(sm + (size_t)(c & 3) * 4096);
        const uint32_t* bs  = sm + (size_t)(c & 3) * 4096 + 2048;
#pragma unroll
        for (int ks = 0; ks < 2; ks++) {
            int w0 = ks * 8 + lc, w4 = w0 + 4;
            uint32_t af[4][4];
#pragma unroll
            for (int mt = 0; mt < 4; mt++) {
                int r = warpM * 64 + mt * 16 + lr;
                int S = ((r >> 1) & 3) << 2;
                af[mt][0] = f2tf(asf[r * 16 + (w0 ^ S)]);
                af[mt][1] = f2tf(asf[(r + 8) * 16 + (w0 ^ S)]);
                af[mt][2] = f2tf(asf[r * 16 + (w4 ^ S)]);
                af[mt][3] = f2tf(asf[(r + 8) * 16 + (w4 ^ S)]);
            }
            uint32_t bf[4][2];
#pragma unroll
            for (int nt = 0; nt < 4; nt++) {
                int n0 = warpN * 32 + nt * 8 + lr;
                int X = lc << 3;
                bf[nt][0] = bs[w0 * 128 + (n0 ^ X)];
                bf[nt][1] = bs[w4 * 128 + (n0 ^ X)];
            }
#pragma unroll
            for (int mt = 0; mt < 4; mt++)
#pragma unroll
                for (int nt = 0; nt < 4; nt++) {
                    asm volatile(
                        "mma.sync.aligned.m16n8k8.row.col.f32.tf32.tf32.f32 "
                        "{%0,%1,%2,%3}, {%4,%5,%6,%7}, {%8,%9}, {%0,%1,%2,%3};"
                        : "+f"(acc[mt][nt][0]), "+f"(acc[mt][nt][1]),
                          "+f"(acc[mt][nt][2]), "+f"(acc[mt][nt][3])
                        : "r"(af[mt][0]), "r"(af[mt][1]), "r"(af[mt][2]), "r"(af[mt][3]),
                          "r"(bf[nt][0]), "r"(bf[nt][1]));
                }
        }
        __syncthreads();
    }

#pragma unroll
    for (int mt = 0; mt < 4; mt++) {
        int r0 = brow + warpM * 64 + mt * 16 + lr;
#pragma unroll
        for (int nt = 0; nt < 4; nt++) {
            int col = bcol + warpN * 32 + nt * 8 + 2 * lc;
            float x0 = acc[mt][nt][0], x1 = acc[mt][nt][1];
            float x2 = acc[mt][nt][2], x3 = acc[mt][nt][3];
            if (EPI == 1) {
                x0 = 0.5f * x0 * (1.0f + erff(x0 * 0.70710678118654752440f));
                x1 = 0.5f * x1 * (1.0f + erff(x1 * 0.70710678118654752440f));
                x2 = 0.5f * x2 * (1.0f + erff(x2 * 0.70710678118654752440f));
                x3 = 0.5f * x3 * (1.0f + erff(x3 * 0.70710678118654752440f));
            }
            if (r0 < M)     *(float2*)&C[(size_t)r0 * N + col]       = make_float2(x0, x1);
            if (r0 + 8 < M) *(float2*)&C[(size_t)(r0 + 8) * N + col] = make_float2(x2, x3);
        }
    }
}

// ---------------- growth scan (split hd across 4 blocks/batch) ------------
__global__ void k_growth_scan(const float* __restrict__ sw,
                              const float* __restrict__ z0,
                              const float* __restrict__ v0) {
    int b = blockIdx.x;
    int hd = blockIdx.y * 128 + threadIdx.x;
    int h = hd >> 6;
    float w = 1.0f / (1.0f + expf(-sw[h]));
    float omw = 1.0f - w;
    float prev = z0[hd];
    float s = v0[hd];
    g_smcat[(size_t)b * (Tt + 1) * Dd + hd] = s;
    const float* vp = g_v + (size_t)b * Tt * Dd + hd;
    float* op = g_smcat + (size_t)b * (Tt + 1) * Dd + Dd + hd;
    for (int t = 0; t < Tt; t++) {
        float val = vp[(size_t)t * Dd];
        float diff = val - prev;
        prev = val;
        s = fmaf(w, s, omw * diff);
        op[(size_t)t * Dd] = s;
    }
}

// ---------------- LayerNorm ----------------
__device__ __forceinline__ float wred(float v) {
#pragma unroll
    for (int o = 16; o > 0; o >>= 1) v += __shfl_xor_sync(0xffffffffu, v, o);
    return v;
}

template <int MODE>
__global__ void k_ln(const float* __restrict__ A, const float* __restrict__ Bm,
                     const float* __restrict__ gg, const float* __restrict__ bb,
                     float* __restrict__ out) {
    int r = blockIdx.x;
    int tid = threadIdx.x;
    const float* arow = A + (size_t)r * Dd;
    const float* brow;
    if (MODE == 0) {
        int b = r >> 10, t = r & 1023;
        brow = Bm + ((size_t)b * (Tt + 1) + t + 1) * Dd;
    } else {
        brow = Bm + (size_t)r * Dd;
    }
    int c0 = tid * 4;
    float4 a = *(const float4*)(arow + c0);
    float4 c = *(const float4*)(brow + c0);
    float x0, x1, x2, x3;
    if (MODE == 0) { x0 = a.x - c.x; x1 = a.y - c.y; x2 = a.z - c.z; x3 = a.w - c.w; }
    else           { x0 = a.x + c.x; x1 = a.y + c.y; x2 = a.z + c.z; x3 = a.w + c.w; }

    __shared__ float red[8];
    float s = x0 + x1 + x2 + x3;
    s = wred(s);
    int wid = tid >> 5, lane = tid & 31;
    if (!lane) red[wid] = s;
    __syncthreads();
    float mu = (red[0] + red[1] + red[2] + red[3]) * (1.0f / 512.0f);
    float d0 = x0 - mu, d1 = x1 - mu, d2 = x2 - mu, d3 = x3 - mu;
    float q = d0 * d0 + d1 * d1 + d2 * d2 + d3 * d3;
    q = wred(q);
    if (!lane) red[4 + wid] = q;
    __syncthreads();
    float var = (red[4] + red[5] + red[6] + red[7]) * (1.0f / 512.0f);
    float inv = rsqrtf(var + 1e-5f);
    float4 g4 = *(const float4*)(gg + c0);
    float4 b4 = *(const float4*)(bb + c0);
    float4 o4;
    o4.x = d0 * inv * g4.x + b4.x;
    o4.y = d1 * inv * g4.y + b4.y;
    o4.z = d2 * inv * g4.z + b4.z;
    o4.w = d3 * inv * g4.w + b4.w;
    *(float4*)(out + (size_t)r * Dd + c0) = o4;
}

// ---------------- small prediction GEMM ----------------
__global__ void k_pred(const float* __restrict__ A, int rows_per_b,
                       const float* __restrict__ W, float* __restrict__ out) {
    __shared__ float ws[Dd * CO];
    int tid = threadIdx.x;
    for (int i = tid; i < Dd * CO; i += 256) ws[i] = W[i];
    __syncthreads();
    int r = blockIdx.x * 256 + tid;
    int b = r >> 10, t = r & 1023;
    const float* a = A + ((size_t)b * rows_per_b + t) * Dd;
    float acc[CO];
#pragma unroll
    for (int c = 0; c < CO; c++) acc[c] = 0.f;
    for (int k = 0; k < Dd; k += 4) {
        float4 av = *(const float4*)(a + k);
#pragma unroll
        for (int c = 0; c < CO; c++) {
            acc[c] = fmaf(av.x, ws[(k + 0) * CO + c], acc[c]);
            acc[c] = fmaf(av.y, ws[(k + 1) * CO + c], acc[c]);
            acc[c] = fmaf(av.z, ws[(k + 2) * CO + c], acc[c]);
            acc[c] = fmaf(av.w, ws[(k + 3) * CO + c], acc[c]);
        }
    }
    float* o = out + (size_t)r * CO;
#pragma unroll
    for (int c = 0; c < CO; c++) o[c] = acc[c];
}

// ---------------- level scan ----------------
__global__ void k_level(const float* __restrict__ level,
                        const float* __restrict__ lsw,
                        const float* __restrict__ lv0,
                        float* __restrict__ out) {
    int tid = threadIdx.x;
    if (tid >= Bq * CO) return;
    int b = tid / CO, c = tid % CO;
    float w = 1.0f / (1.0f + expf(-lsw[c]));
    float omw = 1.0f - w;
    float s = lv0[c];
    float a = 0.f;
    const float* lp = level + (size_t)b * Tt * CO + c;
    const float* gp = g_gp + (size_t)b * Tt * CO + c;
    const float* sp = g_sp + (size_t)b * Tt * CO + c;
    float* op = out + (size_t)b * Tt * CO + c;
    for (int t = 0; t < Tt; t++) {
        float val = lp[t * CO] - sp[t * CO];
        s = fmaf(w, s, omw * val);
        a = w * (a + gp[t * CO]);
        op[t * CO] = s + a;
    }
}

extern "C" void kernel_launch(void* const* d_in, const int* in_sizes, int n_in,
                              void* d_out, int out_size) {
    const float* res   = (const float*)d_in[0];
    const float* level = (const float*)d_in[1];
    const float* in_w  = (const float*)d_in[2];
    const float* out_w = (const float*)d_in[3];
    const float* z0    = (const float*)d_in[4];
    const float* gsw   = (const float*)d_in[5];
    const float* gv0   = (const float*)d_in[6];
    const float* ffw1  = (const float*)d_in[7];
    const float* ffw2  = (const float*)d_in[8];
    const float* n1g   = (const float*)d_in[9];
    const float* n1b   = (const float*)d_in[10];
    const float* n2g   = (const float*)d_in[11];
    const float* n2b   = (const float*)d_in[12];
    const float* gpw   = (const float*)d_in[13];
    const float* spw   = (const float*)d_in[14];
    const float* lsw   = (const float*)d_in[15];
    const float* lv0   = (const float*)d_in[16];
    float* out = (float*)d_out;

    float *p_res1, *p_v, *p_smcat, *p_res2, *p_ffh, *p_ffy, *p_gp, *p_sp, *p_wtf;
    cudaGetSymbolAddress((void**)&p_res1,  g_res1);
    cudaGetSymbolAddress((void**)&p_v,     g_v);
    cudaGetSymbolAddress((void**)&p_smcat, g_smcat);
    cudaGetSymbolAddress((void**)&p_res2,  g_res2);
    cudaGetSymbolAddress((void**)&p_ffh,   g_ffh);
    cudaGetSymbolAddress((void**)&p_ffy,   g_ffy);
    cudaGetSymbolAddress((void**)&p_gp,    g_gp);
    cudaGetSymbolAddress((void**)&p_sp,    g_sp);
    cudaGetSymbolAddress((void**)&p_wtf,   g_wtf);

    cudaFuncSetAttribute(k_dftmm, cudaFuncAttributeMaxDynamicSharedMemorySize, DFT_SMEM);
    cudaFuncSetAttribute(k_mma<0>, cudaFuncAttributeMaxDynamicSharedMemorySize, GM_SMEM);
    cudaFuncSetAttribute(k_mma<1>, cudaFuncAttributeMaxDynamicSharedMemorySize, GM_SMEM);

    // season path: cp.async tensor-core DFT
    k_dftw<<<1024, 256>>>();
    k_xt<<<dim3(Tt / 32, Dd / 32, Bq), dim3(32, 8)>>>(res);
    k_dftmm<<<dim3(4, 8, Bq), 256, DFT_SMEM>>>();
    k_topk1<<<dim3(8, Bq), 512>>>();
    k_topk2<<<Bq, 512>>>();
    k_season<<<dim3(TP / 16, Bq), 512>>>(res, out + SEAS_OFF, p_res1);

    // v = res1 @ in_proj_w   [16384,512] x [512,512]
    k_wtf<<<(Dd * Dd + 255) / 256, 256>>>(in_w, p_wtf, Dd * Dd);
    k_mma<0><<<dim3(Dd / 128, Bq * Tt / 128), 256, GM_SMEM>>>(p_res1, p_wtf, p_v,
                                                              Bq * Tt, Dd, Dd);
    k_growth_scan<<<dim3(Bq, 4), 128>>>(gsw, z0, gv0);
    // growth = smcat @ out_proj_w   [16400,512] x [512,512]
    k_wtf<<<(Dd * Dd + 255) / 256, 256>>>(out_w, p_wtf, Dd * Dd);
    k_mma<0><<<dim3(Dd / 128, (Bq * (Tt + 1) + 127) / 128), 256, GM_SMEM>>>(
        p_smcat, p_wtf, out + GROW_OFF, Bq * (Tt + 1), Dd, Dd);
    k_ln<0><<<Bq * Tt, 128>>>(p_res1, out + GROW_OFF, n1g, n1b, p_res2);
    // ffh = gelu(res2 @ ff_w1)   [16384,512] x [512,2048]
    k_wtf<<<(Dd * LATENT + 255) / 256, 256>>>(ffw1, p_wtf, Dd * LATENT);
    k_mma<1><<<dim3(LATENT / 128, Bq * Tt / 128), 256, GM_SMEM>>>(
        p_res2, p_wtf, p_ffh, Bq * Tt, LATENT, Dd);
    // ffy = ffh @ ff_w2   [16384,2048] x [2048,512]
    k_wtf<<<(LATENT * Dd + 255) / 256, 256>>>(ffw2, p_wtf, LATENT * Dd);
    k_mma<0><<<dim3(Dd / 128, Bq * Tt / 128), 256, GM_SMEM>>>(
        p_ffh, p_wtf, p_ffy, Bq * Tt, Dd, LATENT);
    k_ln<1><<<Bq * Tt, 128>>>(p_res2, p_ffy, n2g, n2b, out + RES3_OFF);
    k_pred<<<(Bq * Tt) / 256, 256>>>(out + GROW_OFF, Tt + 1, gpw, p_gp);
    k_pred<<<(Bq * Tt) / 256, 256>>>(out + SEAS_OFF, TP, spw, p_sp);
    k_level<<<1, 128>>>(level, lsw, lv0, out + LVL_OFF);
}

// round 12
// speedup vs baseline: 1.4324x; 1.4324x over previous
#include <cuda_runtime.h>
#include <cuda_bf16.h>
#include <math.h>
#include <stdint.h>

#define Bq 16
#define Tt 1024
#define Dd 512
#define CO 7
#define PRED 96
#define KK 8
#define LATENT 2048
#define NFREQ 511
#define TP (Tt + PRED)

#define RES3_OFF 0
#define LVL_OFF  (Bq*Tt*Dd)
#define GROW_OFF (LVL_OFF + Bq*Tt*CO)
#define SEAS_OFF (GROW_OFF + Bq*(Tt+1)*Dd)

#define PI2 6.283185307179586476925286766559f

// ---------------- scratch ----------------
__device__ float g_Xre[(size_t)Bq*NFREQ*Dd];
__device__ float g_Xim[(size_t)Bq*NFREQ*Dd];
__device__ int   g_fr[Bq*Dd*KK];
__device__ float g_amp[Bq*Dd*KK];
__device__ float g_ph[Bq*Dd*KK];
__device__ float g_tkv[(size_t)Bq*8*Dd*KK];
__device__ int   g_tki[(size_t)Bq*8*Dd*KK];
__device__ float g_res1[(size_t)Bq*Tt*Dd];
__device__ float g_v[(size_t)Bq*Tt*Dd];
__device__ float g_smcat[(size_t)Bq*(Tt+1)*Dd];
__device__ float g_res2[(size_t)Bq*Tt*Dd];
__device__ float g_ffh[(size_t)Bq*Tt*LATENT];
__device__ float g_ffy[(size_t)Bq*Tt*Dd];
__device__ float g_gp[Bq*Tt*CO];
__device__ float g_sp[Bq*Tt*CO];
// DFT twiddle matrix, hi/lo bf16 split: rows 0..511 cos(f=r+1), 512..1023 -sin
__device__ __nv_bfloat16 g_dwh[(size_t)1024*1024];
__device__ __nv_bfloat16 g_dwl[(size_t)1024*1024];
// x transposed + split: [b][d][t] bf16 hi/lo
__device__ __nv_bfloat16 g_xth[(size_t)Bq*Dd*Tt];
__device__ __nv_bfloat16 g_xtl[(size_t)Bq*Dd*Tt];

// ---------------- helpers ----------------
__device__ __forceinline__ uint32_t f2tf(float x) {
    uint32_t u;
    asm("cvt.rna.tf32.f32 %0, %1;" : "=r"(u) : "f"(x));
    return u;
}
__device__ __forceinline__ float bf_round(float x) {
    return __bfloat162float(__float2bfloat16(x));
}
__device__ __forceinline__ void mma_bf16(float* c, const uint32_t* a, const uint32_t* b) {
    asm volatile(
        "mma.sync.aligned.m16n8k16.row.col.f32.bf16.bf16.f32 "
        "{%0,%1,%2,%3}, {%4,%5,%6,%7}, {%8,%9}, {%0,%1,%2,%3};"
        : "+f"(c[0]), "+f"(c[1]), "+f"(c[2]), "+f"(c[3])
        : "r"(a[0]), "r"(a[1]), "r"(a[2]), "r"(a[3]), "r"(b[0]), "r"(b[1]));
}
__device__ __forceinline__ uint32_t smem_u32(const void* p) {
    uint32_t a;
    asm("{ .reg .u64 t; cvta.to.shared.u64 t, %1; cvt.u32.u64 %0, t; }" : "=r"(a) : "l"(p));
    return a;
}
__device__ __forceinline__ void cp16(uint32_t dst, const void* src, int sz) {
    asm volatile("cp.async.cg.shared.global [%0], [%1], 16, %2;"
                 :: "r"(dst), "l"(src), "r"(sz));
}
#define CP_COMMIT() asm volatile("cp.async.commit_group;")
#define CP_WAIT2()  asm volatile("cp.async.wait_group 2;")

// ---------------- DFT twiddle precompute ----------------
__global__ void k_dftw() {
    for (int e = blockIdx.x * 256 + threadIdx.x; e < 1024 * 1024; e += 262144) {
        int row = e >> 10, t = e & 1023;
        int f = (row < 512) ? row + 1 : row - 511;
        int ph = (f * t) & 1023;
        float ang = (float)ph * (1.0f / 512.0f);
        float v = (row < 512) ? cospif(ang) : -sinpif(ang);
        float h = bf_round(v);
        g_dwh[e] = __float2bfloat16(h);
        g_dwl[e] = __float2bfloat16(v - h);
    }
}

// ---------------- x transpose + hi/lo bf16 split ----------------
__global__ void k_xt(const float* __restrict__ x) {
    __shared__ float t[32][33];
    int b = blockIdx.z;
    int t0 = blockIdx.x * 32, d0 = blockIdx.y * 32;
    int tx = threadIdx.x, ty = threadIdx.y;
    const float* xp = x + (size_t)b * Tt * Dd;
#pragma unroll
    for (int i = 0; i < 32; i += 8)
        t[ty + i][tx] = xp[(size_t)(t0 + ty + i) * Dd + d0 + tx];
    __syncthreads();
#pragma unroll
    for (int i = 0; i < 32; i += 8) {
        float v = t[tx][ty + i];
        float h = bf_round(v);
        size_t o = ((size_t)b * Dd + d0 + ty + i) * Tt + t0 + tx;
        g_xth[o] = __float2bfloat16(h);
        g_xtl[o] = __float2bfloat16(v - h);
    }
}

// ---------------- cp.async tensor-core DFT ----------------
__device__ __forceinline__ void dft_store(int row, int col, float v0, float v1, int b) {
    if (row < 512) {
        if (row < 511)
            *(float2*)&g_Xre[((size_t)b * NFREQ + row) * Dd + col] = make_float2(v0, v1);
    } else {
        int rr = row - 512;
        if (rr < 511)
            *(float2*)&g_Xim[((size_t)b * NFREQ + rr) * Dd + col] = make_float2(v0, v1);
    }
}
__device__ __forceinline__ int dswz(int r, int c) {
    return r * 16 + ((c ^ ((r >> 1) & 3)) << 2);
}

#define DFT_SMEM (3 * 32768)

__global__ __launch_bounds__(256, 2)
void k_dftmm() {
    extern __shared__ uint32_t ds[];
    uint32_t sb = smem_u32(ds);
    int tid = threadIdx.x, lane = tid & 31, warp = tid >> 5;
    int warpM = warp >> 2, warpN = warp & 3;
    int bn = blockIdx.x * 128, bm = blockIdx.y * 128;
    int b = blockIdx.z;

    float acc[4][4][4];
#pragma unroll
    for (int i = 0; i < 4; i++)
#pragma unroll
        for (int j = 0; j < 4; j++)
#pragma unroll
            for (int q = 0; q < 4; q++) acc[i][j][q] = 0.f;

    int crow = tid >> 1;
    int cc0  = (tid & 1) * 2;
    const __nv_bfloat16* ga_h = g_dwh + (size_t)(bm + crow) * 1024;
    const __nv_bfloat16* ga_l = g_dwl + (size_t)(bm + crow) * 1024;
    const __nv_bfloat16* gb_h = g_xth + ((size_t)b * Dd + bn + crow) * Tt;
    const __nv_bfloat16* gb_l = g_xtl + ((size_t)b * Dd + bn + crow) * Tt;
    uint32_t so0 = (uint32_t)dswz(crow, cc0) * 4;
    uint32_t so1 = (uint32_t)dswz(crow, cc0 + 1) * 4;

    auto issue = [&](int c) {
        uint32_t base = sb + (uint32_t)(c % 3) * 32768;
        int k0 = c * 32;
        cp16(base + so0,         ga_h + k0 + cc0 * 8, 16);
        cp16(base + so1,         ga_h + k0 + cc0 * 8 + 8, 16);
        cp16(base + 8192 + so0,  ga_l + k0 + cc0 * 8, 16);
        cp16(base + 8192 + so1,  ga_l + k0 + cc0 * 8 + 8, 16);
        cp16(base + 16384 + so0, gb_h + k0 + cc0 * 8, 16);
        cp16(base + 16384 + so1, gb_h + k0 + cc0 * 8 + 8, 16);
        cp16(base + 24576 + so0, gb_l + k0 + cc0 * 8, 16);
        cp16(base + 24576 + so1, gb_l + k0 + cc0 * 8 + 8, 16);
    };

    issue(0); CP_COMMIT();
    issue(1); CP_COMMIT();
    issue(2); CP_COMMIT();

    int g = lane >> 2, cq = lane & 3;
    for (int c = 0; c < 32; c++) {
        CP_WAIT2();
        __syncthreads();

        const uint32_t* Ah = ds + (size_t)(c % 3) * 8192;
        const uint32_t* Al = Ah + 2048;
        const uint32_t* Bh = Ah + 4096;
        const uint32_t* Bl = Ah + 6144;
#pragma unroll
        for (int ks = 0; ks < 2; ks++) {
            int c0 = ks * 2, c1 = ks * 2 + 1;
            uint32_t af[4][4], bh[4][2], bx[4][2];
#pragma unroll
            for (int mt = 0; mt < 4; mt++) {
                int r = warpM * 64 + mt * 16 + g;
                af[mt][0] = Ah[dswz(r, c0) + cq];
                af[mt][1] = Ah[dswz(r + 8, c0) + cq];
                af[mt][2] = Ah[dswz(r, c1) + cq];
                af[mt][3] = Ah[dswz(r + 8, c1) + cq];
            }
#pragma unroll
            for (int nt = 0; nt < 4; nt++) {
                int n = warpN * 32 + nt * 8 + g;
                bh[nt][0] = Bh[dswz(n, c0) + cq];
                bh[nt][1] = Bh[dswz(n, c1) + cq];
            }
#pragma unroll
            for (int mt = 0; mt < 4; mt++)
#pragma unroll
                for (int nt = 0; nt < 4; nt++) mma_bf16(acc[mt][nt], af[mt], bh[nt]);
#pragma unroll
            for (int nt = 0; nt < 4; nt++) {
                int n = warpN * 32 + nt * 8 + g;
                bx[nt][0] = Bl[dswz(n, c0) + cq];
                bx[nt][1] = Bl[dswz(n, c1) + cq];
            }
#pragma unroll
            for (int mt = 0; mt < 4; mt++)
#pragma unroll
                for (int nt = 0; nt < 4; nt++) mma_bf16(acc[mt][nt], af[mt], bx[nt]);
#pragma unroll
            for (int mt = 0; mt < 4; mt++) {
                int r = warpM * 64 + mt * 16 + g;
                af[mt][0] = Al[dswz(r, c0) + cq];
                af[mt][1] = Al[dswz(r + 8, c0) + cq];
                af[mt][2] = Al[dswz(r, c1) + cq];
                af[mt][3] = Al[dswz(r + 8, c1) + cq];
            }
#pragma unroll
            for (int mt = 0; mt < 4; mt++)
#pragma unroll
                for (int nt = 0; nt < 4; nt++) mma_bf16(acc[mt][nt], af[mt], bh[nt]);
        }
        __syncthreads();
        if (c + 3 < 32) issue(c + 3);
        CP_COMMIT();
    }

#pragma unroll
    for (int mt = 0; mt < 4; mt++) {
        int r0 = bm + warpM * 64 + mt * 16 + g;
#pragma unroll
        for (int nt = 0; nt < 4; nt++) {
            int n0 = bn + warpN * 32 + nt * 8 + 2 * cq;
            dft_store(r0,     n0, acc[mt][nt][0], acc[mt][nt][1], b);
            dft_store(r0 + 8, n0, acc[mt][nt][2], acc[mt][nt][3], b);
        }
    }
}

// ---------------- top-K phase 1: per-chunk top-8 ----------------
__global__ void k_topk1() {
    int d = threadIdx.x;
    int ch = blockIdx.x;
    int b = blockIdx.y;
    int f0 = ch * 64;
    int f1 = f0 + 64 < NFREQ ? f0 + 64 : NFREQ;

    float val[KK];
    int   idx[KK];
#pragma unroll
    for (int k = 0; k < KK; k++) { val[k] = -1.f; idx[k] = 0; }

    for (int f = f0; f < f1; f++) {
        size_t o = ((size_t)b * NFREQ + f) * Dd + d;
        float re = g_Xre[o], im = g_Xim[o];
        float m = re * re + im * im;
        if (m > val[KK - 1]) {
            int p = KK - 1;
            while (p > 0 && m > val[p - 1]) {
                val[p] = val[p - 1]; idx[p] = idx[p - 1]; p--;
            }
            val[p] = m; idx[p] = f;
        }
    }
    size_t base = (((size_t)b * 8 + ch) * Dd + d) * KK;
#pragma unroll
    for (int k = 0; k < KK; k++) {
        g_tkv[base + k] = val[k];
        g_tki[base + k] = idx[k];
    }
}

// ---------------- top-K phase 2: merge 8 sorted chunk lists ----------------
__global__ void k_topk2() {
    int d = threadIdx.x;
    int b = blockIdx.x;
    float val[KK];
    int   idx[KK];
#pragma unroll
    for (int k = 0; k < KK; k++) { val[k] = -1.f; idx[k] = 0; }

    for (int ch = 0; ch < 8; ch++) {
        size_t base = (((size_t)b * 8 + ch) * Dd + d) * KK;
#pragma unroll
        for (int k = 0; k < KK; k++) {
            float m = g_tkv[base + k];
            if (m > val[KK - 1]) {
                int fi = g_tki[base + k];
                int p = KK - 1;
                while (p > 0 && m > val[p - 1]) {
                    val[p] = val[p - 1]; idx[p] = idx[p - 1]; p--;
                }
                val[p] = m; idx[p] = fi;
            } else {
                break;
            }
        }
    }

    int obase = (b * Dd + d) * KK;
#pragma unroll
    for (int k = 0; k < KK; k++) {
        int f = idx[k];
        size_t o = ((size_t)b * NFREQ + f) * Dd + d;
        float re = g_Xre[o], im = g_Xim[o];
        float mag = sqrtf(re * re + im * im);
        g_fr[obase + k]  = f + 1;
        g_amp[obase + k] = 2.0f * mag * (1.0f / 1024.0f);
        g_ph[obase + k]  = atan2f(im, re);
    }
}

// ---------------- season synthesis + res1 ----------------
__global__ void k_season(const float* __restrict__ res,
                         float* __restrict__ season,
                         float* __restrict__ res1) {
    int d = threadIdx.x;
    int b = blockIdx.y;
    int t0 = blockIdx.x * 16;
    int base = (b * Dd + d) * KK;
    int fr[KK]; float am[KK], ph[KK];
#pragma unroll
    for (int k = 0; k < KK; k++) {
        fr[k] = g_fr[base + k]; am[k] = g_amp[base + k]; ph[k] = g_ph[base + k];
    }
    for (int tt = 0; tt < 16; tt++) {
        int t = t0 + tt;
        float sum = 0.f;
#pragma unroll
        for (int k = 0; k < KK; k++) {
            int id = (fr[k] * t) & 1023;
            sum += am[k] * __cosf((float)id * (PI2 / 1024.0f) + ph[k]);
        }
        season[((size_t)b * TP + t) * Dd + d] = sum;
        if (t < Tt) {
            size_t o = ((size_t)b * Tt + t) * Dd + d;
            res1[o] = res[o] - sum;
        }
    }
}

// ================= tf32 cp.async multistage GEMM =================
// C[M,N] = A[M,K] @ W[K,N].  Both operands fp32 in gmem; rna-rounded to tf32
// at fragment load.  BM=BN=128, BK=16, 4 stages x 16KB, 2 blocks/SM.
#define GM_SMEM (4 * 16384)

template <int EPI>
__global__ __launch_bounds__(256, 2)
void k_mma(const float* __restrict__ A, const float* __restrict__ W,
           float* __restrict__ C, int M, int N, int K) {
    extern __shared__ uint32_t sm[];
    uint32_t sb = smem_u32(sm);

    int tid  = threadIdx.x;
    int lane = tid & 31;
    int warp = tid >> 5;
    int warpM = warp >> 2;
    int warpN = warp & 3;
    int brow = blockIdx.y * 128;
    int bcol = blockIdx.x * 128;
    int lr = lane >> 2;
    int lc = lane & 3;

    float acc[4][4][4];
#pragma unroll
    for (int i = 0; i < 4; i++)
#pragma unroll
        for (int j = 0; j < 4; j++)
#pragma unroll
            for (int q = 0; q < 4; q++) acc[i][j][q] = 0.f;

    int am  = tid >> 1;
    int akg = (tid & 1) * 2;
    int asz = (brow + am < M) ? 16 : 0;
    const float* a_base = A + (size_t)(brow + am) * K;
    uint32_t a_off0 = (uint32_t)(am * 16 + (((akg + 0) * 4) ^ (((am >> 1) & 3) << 2))) * 4;
    uint32_t a_off1 = (uint32_t)(am * 16 + (((akg + 1) * 4) ^ (((am >> 1) & 3) << 2))) * 4;

    int bkr = tid >> 4;
    int bn4 = (tid & 15) * 2;
    const float* b_base = W + (size_t)bkr * N + bcol;
    uint32_t b_off0 = (uint32_t)(8192 + (bkr * 128 + (((bn4 + 0) * 4) ^ ((bkr & 3) << 3))) * 4);
    uint32_t b_off1 = (uint32_t)(8192 + (bkr * 128 + (((bn4 + 1) * 4) ^ ((bkr & 3) << 3))) * 4);

    const int NC = K >> 4;

    auto issue = [&](int c) {
        uint32_t base = sb + (uint32_t)(c & 3) * 16384;
        int k0 = c * 16;
        cp16(base + a_off0, a_base + k0 + (akg + 0) * 4, asz);
        cp16(base + a_off1, a_base + k0 + (akg + 1) * 4, asz);
        cp16(base + b_off0, b_base + (size_t)k0 * N + (bn4 + 0) * 4, 16);
        cp16(base + b_off1, b_base + (size_t)k0 * N + (bn4 + 1) * 4, 16);
    };

    issue(0); CP_COMMIT();
    issue(1); CP_COMMIT();
    issue(2); CP_COMMIT();

    for (int c = 0; c < NC; c++) {
        CP_WAIT2();
        __syncthreads();
        if (c + 3 < NC) issue(c + 3);
        CP_COMMIT();

        const float* asf = (const float*)(sm + (size_t)(c & 3) * 4096);
        const float* bsf = (const float*)(sm + (size_t)(c & 3) * 4096 + 2048);
#pragma unroll
        for (int ks = 0; ks < 2; ks++) {
            int w0 = ks * 8 + lc, w4 = w0 + 4;
            uint32_t af[4][4];
#pragma unroll
            for (int mt = 0; mt < 4; mt++) {
                int r = warpM * 64 + mt * 16 + lr;
                int S = ((r >> 1) & 3) << 2;
                af[mt][0] = f2tf(asf[r * 16 + (w0 ^ S)]);
                af[mt][1] = f2tf(asf[(r + 8) * 16 + (w0 ^ S)]);
                af[mt][2] = f2tf(asf[r * 16 + (w4 ^ S)]);
                af[mt][3] = f2tf(asf[(r + 8) * 16 + (w4 ^ S)]);
            }
            uint32_t bf[4][2];
#pragma unroll
            for (int nt = 0; nt < 4; nt++) {
                int n0 = warpN * 32 + nt * 8 + lr;
                int X = lc << 3;
                bf[nt][0] = f2tf(bsf[w0 * 128 + (n0 ^ X)]);
                bf[nt][1] = f2tf(bsf[w4 * 128 + (n0 ^ X)]);
            }
#pragma unroll
            for (int mt = 0; mt < 4; mt++)
#pragma unroll
                for (int nt = 0; nt < 4; nt++) {
                    asm volatile(
                        "mma.sync.aligned.m16n8k8.row.col.f32.tf32.tf32.f32 "
                        "{%0,%1,%2,%3}, {%4,%5,%6,%7}, {%8,%9}, {%0,%1,%2,%3};"
                        : "+f"(acc[mt][nt][0]), "+f"(acc[mt][nt][1]),
                          "+f"(acc[mt][nt][2]), "+f"(acc[mt][nt][3])
                        : "r"(af[mt][0]), "r"(af[mt][1]), "r"(af[mt][2]), "r"(af[mt][3]),
                          "r"(bf[nt][0]), "r"(bf[nt][1]));
                }
        }
        __syncthreads();
    }

#pragma unroll
    for (int mt = 0; mt < 4; mt++) {
        int r0 = brow + warpM * 64 + mt * 16 + lr;
#pragma unroll
        for (int nt = 0; nt < 4; nt++) {
            int col = bcol + warpN * 32 + nt * 8 + 2 * lc;
            float x0 = acc[mt][nt][0], x1 = acc[mt][nt][1];
            float x2 = acc[mt][nt][2], x3 = acc[mt][nt][3];
            if (EPI == 1) {
                x0 = 0.5f * x0 * (1.0f + erff(x0 * 0.70710678118654752440f));
                x1 = 0.5f * x1 * (1.0f + erff(x1 * 0.70710678118654752440f));
                x2 = 0.5f * x2 * (1.0f + erff(x2 * 0.70710678118654752440f));
                x3 = 0.5f * x3 * (1.0f + erff(x3 * 0.70710678118654752440f));
            }
            if (r0 < M)     *(float2*)&C[(size_t)r0 * N + col]       = make_float2(x0, x1);
            if (r0 + 8 < M) *(float2*)&C[(size_t)(r0 + 8) * N + col] = make_float2(x2, x3);
        }
    }
}

// ---------------- growth scan (split hd across 4 blocks/batch) ------------
__global__ void k_growth_scan(const float* __restrict__ sw,
                              const float* __restrict__ z0,
                              const float* __restrict__ v0) {
    int b = blockIdx.x;
    int hd = blockIdx.y * 128 + threadIdx.x;
    int h = hd >> 6;
    float w = 1.0f / (1.0f + expf(-sw[h]));
    float omw = 1.0f - w;
    float prev = z0[hd];
    float s = v0[hd];
    g_smcat[(size_t)b * (Tt + 1) * Dd + hd] = s;
    const float* vp = g_v + (size_t)b * Tt * Dd + hd;
    float* op = g_smcat + (size_t)b * (Tt + 1) * Dd + Dd + hd;
    for (int t = 0; t < Tt; t++) {
        float val = vp[(size_t)t * Dd];
        float diff = val - prev;
        prev = val;
        s = fmaf(w, s, omw * diff);
        op[(size_t)t * Dd] = s;
    }
}

// ---------------- LayerNorm ----------------
__device__ __forceinline__ float wred(float v) {
#pragma unroll
    for (int o = 16; o > 0; o >>= 1) v += __shfl_xor_sync(0xffffffffu, v, o);
    return v;
}

template <int MODE>
__global__ void k_ln(const float* __restrict__ A, const float* __restrict__ Bm,
                     const float* __restrict__ gg, const float* __restrict__ bb,
                     float* __restrict__ out) {
    int r = blockIdx.x;
    int tid = threadIdx.x;
    const float* arow = A + (size_t)r * Dd;
    const float* brow;
    if (MODE == 0) {
        int b = r >> 10, t = r & 1023;
        brow = Bm + ((size_t)b * (Tt + 1) + t + 1) * Dd;
    } else {
        brow = Bm + (size_t)r * Dd;
    }
    int c0 = tid * 4;
    float4 a = *(const float4*)(arow + c0);
    float4 c = *(const float4*)(brow + c0);
    float x0, x1, x2, x3;
    if (MODE == 0) { x0 = a.x - c.x; x1 = a.y - c.y; x2 = a.z - c.z; x3 = a.w - c.w; }
    else           { x0 = a.x + c.x; x1 = a.y + c.y; x2 = a.z + c.z; x3 = a.w + c.w; }

    __shared__ float red[8];
    float s = x0 + x1 + x2 + x3;
    s = wred(s);
    int wid = tid >> 5, lane = tid & 31;
    if (!lane) red[wid] = s;
    __syncthreads();
    float mu = (red[0] + red[1] + red[2] + red[3]) * (1.0f / 512.0f);
    float d0 = x0 - mu, d1 = x1 - mu, d2 = x2 - mu, d3 = x3 - mu;
    float q = d0 * d0 + d1 * d1 + d2 * d2 + d3 * d3;
    q = wred(q);
    if (!lane) red[4 + wid] = q;
    __syncthreads();
    float var = (red[4] + red[5] + red[6] + red[7]) * (1.0f / 512.0f);
    float inv = rsqrtf(var + 1e-5f);
    float4 g4 = *(const float4*)(gg + c0);
    float4 b4 = *(const float4*)(bb + c0);
    float4 o4;
    o4.x = d0 * inv * g4.x + b4.x;
    o4.y = d1 * inv * g4.y + b4.y;
    o4.z = d2 * inv * g4.z + b4.z;
    o4.w = d3 * inv * g4.w + b4.w;
    *(float4*)(out + (size_t)r * Dd + c0) = o4;
}

// ---------------- small prediction GEMM ----------------
__global__ void k_pred(const float* __restrict__ A, int rows_per_b,
                       const float* __restrict__ W, float* __restrict__ out) {
    __shared__ float ws[Dd * CO];
    int tid = threadIdx.x;
    for (int i = tid; i < Dd * CO; i += 256) ws[i] = W[i];
    __syncthreads();
    int r = blockIdx.x * 256 + tid;
    int b = r >> 10, t = r & 1023;
    const float* a = A + ((size_t)b * rows_per_b + t) * Dd;
    float acc[CO];
#pragma unroll
    for (int c = 0; c < CO; c++) acc[c] = 0.f;
    for (int k = 0; k < Dd; k += 4) {
        float4 av = *(const float4*)(a + k);
#pragma unroll
        for (int c = 0; c < CO; c++) {
            acc[c] = fmaf(av.x, ws[(k + 0) * CO + c], acc[c]);
            acc[c] = fmaf(av.y, ws[(k + 1) * CO + c], acc[c]);
            acc[c] = fmaf(av.z, ws[(k + 2) * CO + c], acc[c]);
            acc[c] = fmaf(av.w, ws[(k + 3) * CO + c], acc[c]);
        }
    }
    float* o = out + (size_t)r * CO;
#pragma unroll
    for (int c = 0; c < CO; c++) o[c] = acc[c];
}

// ---------------- level scan ----------------
__global__ void k_level(const float* __restrict__ level,
                        const float* __restrict__ lsw,
                        const float* __restrict__ lv0,
                        float* __restrict__ out) {
    int tid = threadIdx.x;
    if (tid >= Bq * CO) return;
    int b = tid / CO, c = tid % CO;
    float w = 1.0f / (1.0f + expf(-lsw[c]));
    float omw = 1.0f - w;
    float s = lv0[c];
    float a = 0.f;
    const float* lp = level + (size_t)b * Tt * CO + c;
    const float* gp = g_gp + (size_t)b * Tt * CO + c;
    const float* sp = g_sp + (size_t)b * Tt * CO + c;
    float* op = out + (size_t)b * Tt * CO + c;
    for (int t = 0; t < Tt; t++) {
        float val = lp[t * CO] - sp[t * CO];
        s = fmaf(w, s, omw * val);
        a = w * (a + gp[t * CO]);
        op[t * CO] = s + a;
    }
}

extern "C" void kernel_launch(void* const* d_in, const int* in_sizes, int n_in,
                              void* d_out, int out_size) {
    const float* res   = (const float*)d_in[0];
    const float* level = (const float*)d_in[1];
    const float* in_w  = (const float*)d_in[2];
    const float* out_w = (const float*)d_in[3];
    const float* z0    = (const float*)d_in[4];
    const float* gsw   = (const float*)d_in[5];
    const float* gv0   = (const float*)d_in[6];
    const float* ffw1  = (const float*)d_in[7];
    const float* ffw2  = (const float*)d_in[8];
    const float* n1g   = (const float*)d_in[9];
    const float* n1b   = (const float*)d_in[10];
    const float* n2g   = (const float*)d_in[11];
    const float* n2b   = (const float*)d_in[12];
    const float* gpw   = (const float*)d_in[13];
    const float* spw   = (const float*)d_in[14];
    const float* lsw   = (const float*)d_in[15];
    const float* lv0   = (const float*)d_in[16];
    float* out = (float*)d_out;

    float *p_res1, *p_v, *p_smcat, *p_res2, *p_ffh, *p_ffy, *p_gp, *p_sp;
    cudaGetSymbolAddress((void**)&p_res1,  g_res1);
    cudaGetSymbolAddress((void**)&p_v,     g_v);
    cudaGetSymbolAddress((void**)&p_smcat, g_smcat);
    cudaGetSymbolAddress((void**)&p_res2,  g_res2);
    cudaGetSymbolAddress((void**)&p_ffh,   g_ffh);
    cudaGetSymbolAddress((void**)&p_ffy,   g_ffy);
    cudaGetSymbolAddress((void**)&p_gp,    g_gp);
    cudaGetSymbolAddress((void**)&p_sp,    g_sp);

    cudaFuncSetAttribute(k_dftmm, cudaFuncAttributeMaxDynamicSharedMemorySize, DFT_SMEM);
    cudaFuncSetAttribute(k_mma<0>, cudaFuncAttributeMaxDynamicSharedMemorySize, GM_SMEM);
    cudaFuncSetAttribute(k_mma<1>, cudaFuncAttributeMaxDynamicSharedMemorySize, GM_SMEM);

    // season path: cp.async tensor-core DFT
    k_dftw<<<1024, 256>>>();
    k_xt<<<dim3(Tt / 32, Dd / 32, Bq), dim3(32, 8)>>>(res);
    k_dftmm<<<dim3(4, 8, Bq), 256, DFT_SMEM>>>();
    k_topk1<<<dim3(8, Bq), 512>>>();
    k_topk2<<<Bq, 512>>>();
    k_season<<<dim3(TP / 16, Bq), 512>>>(res, out + SEAS_OFF, p_res1);

    // v = res1 @ in_proj_w   [16384,512] x [512,512]
    k_mma<0><<<dim3(Dd / 128, Bq * Tt / 128), 256, GM_SMEM>>>(p_res1, in_w, p_v,
                                                              Bq * Tt, Dd, Dd);
    k_growth_scan<<<dim3(Bq, 4), 128>>>(gsw, z0, gv0);
    // growth = smcat @ out_proj_w   [16400,512] x [512,512]
    k_mma<0><<<dim3(Dd / 128, (Bq * (Tt + 1) + 127) / 128), 256, GM_SMEM>>>(
        p_smcat, out_w, out + GROW_OFF, Bq * (Tt + 1), Dd, Dd);
    k_ln<0><<<Bq * Tt, 128>>>(p_res1, out + GROW_OFF, n1g, n1b, p_res2);
    // ffh = gelu(res2 @ ff_w1)   [16384,512] x [512,2048]
    k_mma<1><<<dim3(LATENT / 128, Bq * Tt / 128), 256, GM_SMEM>>>(
        p_res2, ffw1, p_ffh, Bq * Tt, LATENT, Dd);
    // ffy = ffh @ ff_w2   [16384,2048] x [2048,512]
    k_mma<0><<<dim3(Dd / 128, Bq * Tt / 128), 256, GM_SMEM>>>(
        p_ffh, ffw2, p_ffy, Bq * Tt, Dd, LATENT);
    k_ln<1><<<Bq * Tt, 128>>>(p_res2, p_ffy, n2g, n2b, out + RES3_OFF);
    k_pred<<<(Bq * Tt) / 256, 256>>>(out + GROW_OFF, Tt + 1, gpw, p_gp);
    k_pred<<<(Bq * Tt) / 256, 256>>>(out + SEAS_OFF, TP, spw, p_sp);
    k_level<<<1, 128>>>(level, lsw, lv0, out + LVL_OFF);
}